// round 1
// baseline (speedup 1.0000x reference)
#include <cuda_runtime.h>

// Point-transformer fused kernel for GB300 (sm_103a).
// B*G = 16384 groups, 16 neighbors, dim 3.
// One thread per (group, point i); 4 groups per 64-thread block.

#define GPB 4
#define NTHR (GPB * 16)
#define NBLOCKS (16384 / GPB)
#define ASTRIDE 68  // 64 + 4 pad: conflict-free float4 rows

// ---- shared memory layout (float offsets) ----
#define OFF_WQKV 0      // 27
#define OFF_PW1  32     // 192
#define OFF_PB1  224    // 64   (16B aligned for float4)
#define OFF_PW2  288    // 192  (16B aligned for float4)
#define OFF_PB2  480    // 3
#define OFF_AW1  484    // 36
#define OFF_AB1  520    // 12
#define OFF_AW2  532    // 36
#define OFF_AB2  568    // 3
#define OFF_MB1  572    // 48
#define OFF_MB2  620    // 48
#define OFF_MW3  668    // 48
#define OFF_MB3  716    // 1
#define OFF_MW1  720    // 2304
#define OFF_MW2  3024   // 2304
#define OFF_A    5328   // GPB * 16 * ASTRIDE   (16B aligned)
#define OFF_K    (OFF_A + GPB * 16 * ASTRIDE)   // GPB*48
#define OFF_KV   (OFF_K + GPB * 48)             // GPB*48
#define OFF_SA   (OFF_KV + GPB * 48)            // GPB*48
#define OFF_H1   (OFF_SA + GPB * 48)            // GPB*48
#define SMEM_FLOATS (OFF_H1 + GPB * 48)

#define LOADW(PTR, OFF, N)                                        \
    for (int idx_ = tid; idx_ < (N); idx_ += NTHR) sm[(OFF) + idx_] = (PTR)[idx_];

__global__ __launch_bounds__(NTHR, 5)
void pt_kernel(const float* __restrict__ data,
               const float* __restrict__ wqkv,
               const float* __restrict__ pw1, const float* __restrict__ pb1,
               const float* __restrict__ pw2, const float* __restrict__ pb2,
               const float* __restrict__ aw1, const float* __restrict__ ab1,
               const float* __restrict__ aw2, const float* __restrict__ ab2,
               const float* __restrict__ mw1, const float* __restrict__ mb1,
               const float* __restrict__ mw2, const float* __restrict__ mb2,
               const float* __restrict__ mw3, const float* __restrict__ mb3,
               float* __restrict__ out)
{
    extern __shared__ float sm[];
    const int tid = threadIdx.x;
    const int g = tid >> 4;   // group within block
    const int i = tid & 15;   // point index within group

    // ---- phase 1a: stage all weights into shared ----
    LOADW(wqkv, OFF_WQKV, 27)
    LOADW(pw1, OFF_PW1, 192)
    LOADW(pb1, OFF_PB1, 64)
    LOADW(pw2, OFF_PW2, 192)
    LOADW(pb2, OFF_PB2, 3)
    LOADW(aw1, OFF_AW1, 36)
    LOADW(ab1, OFF_AB1, 12)
    LOADW(aw2, OFF_AW2, 36)
    LOADW(ab2, OFF_AB2, 3)
    LOADW(mb1, OFF_MB1, 48)
    LOADW(mb2, OFF_MB2, 48)
    LOADW(mw3, OFF_MW3, 48)
    LOADW(mb3, OFF_MB3, 1)
    LOADW(mw1, OFF_MW1, 2304)
    LOADW(mw2, OFF_MW2, 2304)

    const int bg = blockIdx.x * GPB + g;
    const float* xp = data + (size_t)bg * 48 + i * 3;
    const float x0 = xp[0], x1 = xp[1], x2 = xp[2];

    __syncthreads();

    // ---- phase 1b: per-point q,k,v and pos-hidden precompute a[i][h] ----
    const float* W = sm + OFF_WQKV;  // [3][9]: q cols 0-2, k cols 3-5, v cols 6-8
    const float q0 = fmaf(x2, W[18 + 0], fmaf(x1, W[9 + 0], x0 * W[0]));
    const float q1 = fmaf(x2, W[18 + 1], fmaf(x1, W[9 + 1], x0 * W[1]));
    const float q2 = fmaf(x2, W[18 + 2], fmaf(x1, W[9 + 2], x0 * W[2]));
    const float k0 = fmaf(x2, W[18 + 3], fmaf(x1, W[9 + 3], x0 * W[3]));
    const float k1 = fmaf(x2, W[18 + 4], fmaf(x1, W[9 + 4], x0 * W[4]));
    const float k2 = fmaf(x2, W[18 + 5], fmaf(x1, W[9 + 5], x0 * W[5]));
    const float v0 = fmaf(x2, W[18 + 6], fmaf(x1, W[9 + 6], x0 * W[6]));
    const float v1 = fmaf(x2, W[18 + 7], fmaf(x1, W[9 + 7], x0 * W[7]));
    const float v2 = fmaf(x2, W[18 + 8], fmaf(x1, W[9 + 8], x0 * W[8]));

    {
        float* kW = sm + OFF_K + g * 48 + i * 3;
        kW[0] = k0; kW[1] = k1; kW[2] = k2;
        float* kvW = sm + OFF_KV + g * 48 + i * 3;
        kvW[0] = k0 + v0; kvW[1] = k1 + v1; kvW[2] = k2 + v2;
        float* aW = sm + OFF_A + (g * 16 + i) * ASTRIDE;
        const float* P1 = sm + OFF_PW1;  // [3][64]
        #pragma unroll 8
        for (int h = 0; h < 64; h++) {
            aW[h] = fmaf(x2, P1[128 + h], fmaf(x1, P1[64 + h], x0 * P1[h]));
        }
    }
    __syncthreads();

    // ---- phase 2: rel_emb accumulation; thread i holds re[j][3] in registers ----
    float re[48];
    {
        const float pb20 = sm[OFF_PB2 + 0], pb21 = sm[OFF_PB2 + 1], pb22 = sm[OFF_PB2 + 2];
        #pragma unroll
        for (int j = 0; j < 16; j++) {
            re[j * 3 + 0] = pb20; re[j * 3 + 1] = pb21; re[j * 3 + 2] = pb22;
        }
    }
    {
        const float4* aG = (const float4*)(sm + OFF_A + g * 16 * ASTRIDE);
        const float4* aI = (const float4*)(sm + OFF_A + (g * 16 + i) * ASTRIDE);
        const float4* b1v4 = (const float4*)(sm + OFF_PB1);
        const float4* w2v4 = (const float4*)(sm + OFF_PW2);
        #pragma unroll 1
        for (int hq = 0; hq < 16; hq++) {
            const float4 ai = aI[hq];
            const float4 bb = b1v4[hq];
            const float ai0 = ai.x + bb.x, ai1 = ai.y + bb.y;
            const float ai2 = ai.z + bb.z, ai3 = ai.w + bb.w;
            // pos_w2 rows h..h+3 (12 floats) as 3 float4s
            const float4 wA = w2v4[hq * 3 + 0];
            const float4 wB = w2v4[hq * 3 + 1];
            const float4 wC = w2v4[hq * 3 + 2];
            #pragma unroll
            for (int j = 0; j < 16; j++) {
                const float4 aj = aG[j * (ASTRIDE / 4) + hq];
                const float e0 = fmaxf(ai0 - aj.x, 0.f);
                const float e1 = fmaxf(ai1 - aj.y, 0.f);
                const float e2 = fmaxf(ai2 - aj.z, 0.f);
                const float e3 = fmaxf(ai3 - aj.w, 0.f);
                float r0 = re[j * 3 + 0], r1 = re[j * 3 + 1], r2 = re[j * 3 + 2];
                r0 = fmaf(e0, wA.x, r0); r1 = fmaf(e0, wA.y, r1); r2 = fmaf(e0, wA.z, r2);
                r0 = fmaf(e1, wA.w, r0); r1 = fmaf(e1, wB.x, r1); r2 = fmaf(e1, wB.y, r2);
                r0 = fmaf(e2, wB.z, r0); r1 = fmaf(e2, wB.w, r1); r2 = fmaf(e2, wC.x, r2);
                r0 = fmaf(e3, wC.y, r0); r1 = fmaf(e3, wC.z, r1); r2 = fmaf(e3, wC.w, r2);
                re[j * 3 + 0] = r0; re[j * 3 + 1] = r1; re[j * 3 + 2] = r2;
            }
        }
    }

    // ---- phase 3: attention MLP. Convert re -> t = q_i - k_j + re (in place) ----
    const float* kS = sm + OFF_K + g * 48;
    const float* kvS = sm + OFF_KV + g * 48;
    #pragma unroll
    for (int j = 0; j < 16; j++) {
        re[j * 3 + 0] += q0 - kS[j * 3 + 0];
        re[j * 3 + 1] += q1 - kS[j * 3 + 1];
        re[j * 3 + 2] += q2 - kS[j * 3 + 2];
    }
    float sim[48];
    {
        const float ab20 = sm[OFF_AB2 + 0], ab21 = sm[OFF_AB2 + 1], ab22 = sm[OFF_AB2 + 2];
        #pragma unroll
        for (int j = 0; j < 16; j++) {
            sim[j * 3 + 0] = ab20; sim[j * 3 + 1] = ab21; sim[j * 3 + 2] = ab22;
        }
    }
    #pragma unroll 1
    for (int c = 0; c < 12; c++) {
        const float w10 = sm[OFF_AW1 + c];
        const float w11 = sm[OFF_AW1 + 12 + c];
        const float w12 = sm[OFF_AW1 + 24 + c];
        const float bb = sm[OFF_AB1 + c];
        const float w20 = sm[OFF_AW2 + c * 3 + 0];
        const float w21 = sm[OFF_AW2 + c * 3 + 1];
        const float w22 = sm[OFF_AW2 + c * 3 + 2];
        #pragma unroll
        for (int j = 0; j < 16; j++) {
            float u = fmaf(re[j * 3 + 2], w12,
                     fmaf(re[j * 3 + 1], w11,
                     fmaf(re[j * 3 + 0], w10, bb)));
            u = fmaxf(u, 0.f);
            sim[j * 3 + 0] = fmaf(u, w20, sim[j * 3 + 0]);
            sim[j * 3 + 1] = fmaf(u, w21, sim[j * 3 + 1]);
            sim[j * 3 + 2] = fmaf(u, w22, sim[j * 3 + 2]);
        }
    }

    // ---- phase 4: softmax over j (per d) + aggregation, fully in-register ----
    float agg[3];
    #pragma unroll
    for (int d = 0; d < 3; d++) {
        const float qd = (d == 0) ? q0 : ((d == 1) ? q1 : q2);
        float m = -3.4e38f;
        #pragma unroll
        for (int j = 0; j < 16; j++) m = fmaxf(m, sim[j * 3 + d]);
        float s = 0.f, acc = 0.f;
        #pragma unroll
        for (int j = 0; j < 16; j++) {
            const float p = __expf(sim[j * 3 + d] - m);
            s += p;
            // v_ij = v_j + re = t + (k_j + v_j) - q_i
            const float vij = re[j * 3 + d] + kvS[j * 3 + d] - qd;
            acc = fmaf(p, vij, acc);
        }
        agg[d] = acc / s;
    }
    {
        float* saW = sm + OFF_SA + g * 48 + i * 3;
        saW[0] = agg[0]; saW[1] = agg[1]; saW[2] = agg[2];
    }
    __syncwarp();

    // ---- phase 5: MLP head 48 -> 48 -> 48 -> 1 (16 threads per group, 3 outputs each) ----
    const float* saS = sm + OFF_SA + g * 48;
    const float* W1s = sm + OFF_MW1;
    float h1a = sm[OFF_MB1 + i], h1b = sm[OFF_MB1 + i + 16], h1c = sm[OFF_MB1 + i + 32];
    #pragma unroll 4
    for (int kk = 0; kk < 48; kk++) {
        const float sv = saS[kk];
        h1a = fmaf(sv, W1s[kk * 48 + i], h1a);
        h1b = fmaf(sv, W1s[kk * 48 + i + 16], h1b);
        h1c = fmaf(sv, W1s[kk * 48 + i + 32], h1c);
    }
    h1a = fmaxf(h1a, 0.f); h1b = fmaxf(h1b, 0.f); h1c = fmaxf(h1c, 0.f);
    {
        float* h1W = sm + OFF_H1 + g * 48;
        h1W[i] = h1a; h1W[i + 16] = h1b; h1W[i + 32] = h1c;
    }
    __syncwarp();

    const float* h1S = sm + OFF_H1 + g * 48;
    const float* W2s = sm + OFF_MW2;
    float h2a = sm[OFF_MB2 + i], h2b = sm[OFF_MB2 + i + 16], h2c = sm[OFF_MB2 + i + 32];
    #pragma unroll 4
    for (int kk = 0; kk < 48; kk++) {
        const float hv = h1S[kk];
        h2a = fmaf(hv, W2s[kk * 48 + i], h2a);
        h2b = fmaf(hv, W2s[kk * 48 + i + 16], h2b);
        h2c = fmaf(hv, W2s[kk * 48 + i + 32], h2c);
    }
    h2a = fmaxf(h2a, 0.f); h2b = fmaxf(h2b, 0.f); h2c = fmaxf(h2c, 0.f);

    float pw = fmaf(h2c, sm[OFF_MW3 + i + 32],
               fmaf(h2b, sm[OFF_MW3 + i + 16],
                    h2a * sm[OFF_MW3 + i]));
    pw += __shfl_xor_sync(0xffffffffu, pw, 8);
    pw += __shfl_xor_sync(0xffffffffu, pw, 4);
    pw += __shfl_xor_sync(0xffffffffu, pw, 2);
    pw += __shfl_xor_sync(0xffffffffu, pw, 1);
    if (i == 0) out[bg] = pw + sm[OFF_MB3];
}

extern "C" void kernel_launch(void* const* d_in, const int* in_sizes, int n_in,
                              void* d_out, int out_size) {
    // metadata order: original_points(unused), data, w_qkv, pos_w1, pos_b1, pos_w2,
    // pos_b2, attn_w1, attn_b1, attn_w2, attn_b2, mlp_w1, mlp_b1, mlp_w2, mlp_b2,
    // mlp_w3, mlp_b3
    const float* data = (const float*)d_in[1];
    const float* wqkv = (const float*)d_in[2];
    const float* pw1  = (const float*)d_in[3];
    const float* pb1  = (const float*)d_in[4];
    const float* pw2  = (const float*)d_in[5];
    const float* pb2  = (const float*)d_in[6];
    const float* aw1  = (const float*)d_in[7];
    const float* ab1  = (const float*)d_in[8];
    const float* aw2  = (const float*)d_in[9];
    const float* ab2  = (const float*)d_in[10];
    const float* mw1  = (const float*)d_in[11];
    const float* mb1  = (const float*)d_in[12];
    const float* mw2  = (const float*)d_in[13];
    const float* mb2  = (const float*)d_in[14];
    const float* mw3  = (const float*)d_in[15];
    const float* mb3  = (const float*)d_in[16];
    float* out = (float*)d_out;

    const size_t smem = SMEM_FLOATS * sizeof(float);  // ~41.8 KB, under 48 KB default
    pt_kernel<<<NBLOCKS, NTHR, smem>>>(data, wqkv, pw1, pb1, pw2, pb2,
                                       aw1, ab1, aw2, ab2,
                                       mw1, mb1, mw2, mb2, mw3, mb3, out);
}

// round 2
// speedup vs baseline: 1.3675x; 1.3675x over previous
#include <cuda_runtime.h>

// Point-transformer fused kernel for GB300 (sm_103a).
// B*G = 16384 groups, 16 neighbors, dim 3.
// 32 threads per group (thread = (point i, j-half)); 4 groups per 128-thread block.

#define GPB 4
#define NTHR 128
#define NBLOCKS (16384 / GPB)
#define ASTRIDE 68  // 64 + 4 pad

// ---- shared memory layout (float offsets) ----
#define OFF_WQKV 0      // 27
#define OFF_PW1  32     // 192
#define OFF_PB1  224    // 64   (16B aligned)
#define OFF_PW2  288    // 192  (16B aligned)
#define OFF_PB2  480    // 3
#define OFF_AW1  484    // 36
#define OFF_AB1  520    // 12
#define OFF_AW2  532    // 36
#define OFF_AB2  568    // 3
#define OFF_MB1  572    // 48
#define OFF_MB2  620    // 48
#define OFF_MW3  668    // 48
#define OFF_MB3  716    // 1
#define OFF_MW1  720    // 2304
#define OFF_MW2  3024   // 2304
#define OFF_A    5328   // GPB * 16 * ASTRIDE   (16B aligned)
#define OFF_K    (OFF_A + GPB * 16 * ASTRIDE)   // GPB*48
#define OFF_KV   (OFF_K + GPB * 48)             // GPB*48
#define OFF_SA   (OFF_KV + GPB * 48)            // GPB*48
#define OFF_H1   (OFF_SA + GPB * 48)            // GPB*48
#define SMEM_FLOATS (OFF_H1 + GPB * 48)

#define LOADW(PTR, OFF, N)                                        \
    for (int idx_ = tid; idx_ < (N); idx_ += NTHR) sm[(OFF) + idx_] = (PTR)[idx_];

__global__ __launch_bounds__(NTHR, 5)
void pt_kernel(const float* __restrict__ data,
               const float* __restrict__ wqkv,
               const float* __restrict__ pw1, const float* __restrict__ pb1,
               const float* __restrict__ pw2, const float* __restrict__ pb2,
               const float* __restrict__ aw1, const float* __restrict__ ab1,
               const float* __restrict__ aw2, const float* __restrict__ ab2,
               const float* __restrict__ mw1, const float* __restrict__ mb1,
               const float* __restrict__ mw2, const float* __restrict__ mb2,
               const float* __restrict__ mw3, const float* __restrict__ mb3,
               float* __restrict__ out)
{
    extern __shared__ float sm[];
    const int tid = threadIdx.x;
    const int g = tid >> 5;     // group = warp
    const int lg = tid & 31;    // lane in group
    const int i = lg & 15;      // point index
    const int half = lg >> 4;   // which 8 j's this thread owns

    // ---- phase 1a: stage all weights into shared ----
    LOADW(wqkv, OFF_WQKV, 27)
    LOADW(pw1, OFF_PW1, 192)
    LOADW(pb1, OFF_PB1, 64)
    LOADW(pw2, OFF_PW2, 192)
    LOADW(pb2, OFF_PB2, 3)
    LOADW(aw1, OFF_AW1, 36)
    LOADW(ab1, OFF_AB1, 12)
    LOADW(aw2, OFF_AW2, 36)
    LOADW(ab2, OFF_AB2, 3)
    LOADW(mb1, OFF_MB1, 48)
    LOADW(mb2, OFF_MB2, 48)
    LOADW(mw3, OFF_MW3, 48)
    LOADW(mb3, OFF_MB3, 1)
    LOADW(mw1, OFF_MW1, 2304)
    LOADW(mw2, OFF_MW2, 2304)

    const int bg = blockIdx.x * GPB + g;
    const float* xp = data + (size_t)bg * 48 + i * 3;
    const float x0 = xp[0], x1 = xp[1], x2 = xp[2];

    __syncthreads();

    // ---- phase 1b: per-point q,k,v; pos-hidden a[i][h] (each half does 32 h) ----
    const float* W = sm + OFF_WQKV;  // [3][9]: q cols 0-2, k 3-5, v 6-8
    const float q0 = fmaf(x2, W[18 + 0], fmaf(x1, W[9 + 0], x0 * W[0]));
    const float q1 = fmaf(x2, W[18 + 1], fmaf(x1, W[9 + 1], x0 * W[1]));
    const float q2 = fmaf(x2, W[18 + 2], fmaf(x1, W[9 + 2], x0 * W[2]));
    const float k0 = fmaf(x2, W[18 + 3], fmaf(x1, W[9 + 3], x0 * W[3]));
    const float k1 = fmaf(x2, W[18 + 4], fmaf(x1, W[9 + 4], x0 * W[4]));
    const float k2 = fmaf(x2, W[18 + 5], fmaf(x1, W[9 + 5], x0 * W[5]));
    const float v0 = fmaf(x2, W[18 + 6], fmaf(x1, W[9 + 6], x0 * W[6]));
    const float v1 = fmaf(x2, W[18 + 7], fmaf(x1, W[9 + 7], x0 * W[7]));
    const float v2 = fmaf(x2, W[18 + 8], fmaf(x1, W[9 + 8], x0 * W[8]));

    if (half == 0) {
        float* kW = sm + OFF_K + g * 48 + i * 3;
        kW[0] = k0; kW[1] = k1; kW[2] = k2;
        float* kvW = sm + OFF_KV + g * 48 + i * 3;
        kvW[0] = k0 + v0; kvW[1] = k1 + v1; kvW[2] = k2 + v2;
    }
    {
        float* aW = sm + OFF_A + (g * 16 + i) * ASTRIDE + half * 32;
        const float* P1 = sm + OFF_PW1 + half * 32;  // [3][64] slice
        #pragma unroll 8
        for (int h = 0; h < 32; h++) {
            aW[h] = fmaf(x2, P1[128 + h], fmaf(x1, P1[64 + h], x0 * P1[h]));
        }
    }
    __syncthreads();

    // ---- phase 2: rel_emb for this thread's 8 j's (re[jj][3] in registers) ----
    float re[24];
    {
        const float pb20 = sm[OFF_PB2 + 0], pb21 = sm[OFF_PB2 + 1], pb22 = sm[OFF_PB2 + 2];
        #pragma unroll
        for (int jj = 0; jj < 8; jj++) {
            re[jj * 3 + 0] = pb20; re[jj * 3 + 1] = pb21; re[jj * 3 + 2] = pb22;
        }
    }
    {
        const float4* aJ = (const float4*)(sm + OFF_A + (g * 16 + half * 8) * ASTRIDE);
        const float4* aI = (const float4*)(sm + OFF_A + (g * 16 + i) * ASTRIDE);
        const float4* b1v4 = (const float4*)(sm + OFF_PB1);
        const float4* w2v4 = (const float4*)(sm + OFF_PW2);
        #pragma unroll 1
        for (int hq = 0; hq < 16; hq++) {
            const float4 ai = aI[hq];
            const float4 bb = b1v4[hq];
            const float ai0 = ai.x + bb.x, ai1 = ai.y + bb.y;
            const float ai2 = ai.z + bb.z, ai3 = ai.w + bb.w;
            const float4 wA = w2v4[hq * 3 + 0];
            const float4 wB = w2v4[hq * 3 + 1];
            const float4 wC = w2v4[hq * 3 + 2];
            #pragma unroll
            for (int jj = 0; jj < 8; jj++) {
                const float4 aj = aJ[jj * (ASTRIDE / 4) + hq];
                const float e0 = fmaxf(ai0 - aj.x, 0.f);
                const float e1 = fmaxf(ai1 - aj.y, 0.f);
                const float e2 = fmaxf(ai2 - aj.z, 0.f);
                const float e3 = fmaxf(ai3 - aj.w, 0.f);
                float r0 = re[jj * 3 + 0], r1 = re[jj * 3 + 1], r2 = re[jj * 3 + 2];
                r0 = fmaf(e0, wA.x, r0); r1 = fmaf(e0, wA.y, r1); r2 = fmaf(e0, wA.z, r2);
                r0 = fmaf(e1, wA.w, r0); r1 = fmaf(e1, wB.x, r1); r2 = fmaf(e1, wB.y, r2);
                r0 = fmaf(e2, wB.z, r0); r1 = fmaf(e2, wB.w, r1); r2 = fmaf(e2, wC.x, r2);
                r0 = fmaf(e3, wC.y, r0); r1 = fmaf(e3, wC.z, r1); r2 = fmaf(e3, wC.w, r2);
                re[jj * 3 + 0] = r0; re[jj * 3 + 1] = r1; re[jj * 3 + 2] = r2;
            }
        }
    }

    // ---- phase 3: t = q_i - k_j + rel_emb; attention MLP 3->12->3 ----
    const float* kS  = sm + OFF_K  + g * 48 + half * 24;
    const float* kvS = sm + OFF_KV + g * 48 + half * 24;
    #pragma unroll
    for (int jj = 0; jj < 8; jj++) {
        re[jj * 3 + 0] += q0 - kS[jj * 3 + 0];
        re[jj * 3 + 1] += q1 - kS[jj * 3 + 1];
        re[jj * 3 + 2] += q2 - kS[jj * 3 + 2];
    }
    float sim[24];
    {
        const float ab20 = sm[OFF_AB2 + 0], ab21 = sm[OFF_AB2 + 1], ab22 = sm[OFF_AB2 + 2];
        #pragma unroll
        for (int jj = 0; jj < 8; jj++) {
            sim[jj * 3 + 0] = ab20; sim[jj * 3 + 1] = ab21; sim[jj * 3 + 2] = ab22;
        }
    }
    #pragma unroll 1
    for (int c = 0; c < 12; c++) {
        const float w10 = sm[OFF_AW1 + c];
        const float w11 = sm[OFF_AW1 + 12 + c];
        const float w12 = sm[OFF_AW1 + 24 + c];
        const float bb = sm[OFF_AB1 + c];
        const float w20 = sm[OFF_AW2 + c * 3 + 0];
        const float w21 = sm[OFF_AW2 + c * 3 + 1];
        const float w22 = sm[OFF_AW2 + c * 3 + 2];
        #pragma unroll
        for (int jj = 0; jj < 8; jj++) {
            float u = fmaf(re[jj * 3 + 2], w12,
                     fmaf(re[jj * 3 + 1], w11,
                     fmaf(re[jj * 3 + 0], w10, bb)));
            u = fmaxf(u, 0.f);
            sim[jj * 3 + 0] = fmaf(u, w20, sim[jj * 3 + 0]);
            sim[jj * 3 + 1] = fmaf(u, w21, sim[jj * 3 + 1]);
            sim[jj * 3 + 2] = fmaf(u, w22, sim[jj * 3 + 2]);
        }
    }

    // ---- phase 4: softmax over 16 j (8 local + partner half via shfl) ----
    float agg[3];
    #pragma unroll
    for (int d = 0; d < 3; d++) {
        const float qd = (d == 0) ? q0 : ((d == 1) ? q1 : q2);
        float pm = sim[d];
        #pragma unroll
        for (int jj = 1; jj < 8; jj++) pm = fmaxf(pm, sim[jj * 3 + d]);
        const float m = fmaxf(pm, __shfl_xor_sync(0xffffffffu, pm, 16));
        float s = 0.f, acc = 0.f;
        #pragma unroll
        for (int jj = 0; jj < 8; jj++) {
            const float p = __expf(sim[jj * 3 + d] - m);
            s += p;
            // v_ij = v_j + rel_emb = t + (k_j + v_j) - q_i
            const float vij = re[jj * 3 + d] + kvS[jj * 3 + d] - qd;
            acc = fmaf(p, vij, acc);
        }
        s   += __shfl_xor_sync(0xffffffffu, s, 16);
        acc += __shfl_xor_sync(0xffffffffu, acc, 16);
        agg[d] = acc / s;
    }
    if (half == 0) {
        float* saW = sm + OFF_SA + g * 48 + i * 3;
        saW[0] = agg[0]; saW[1] = agg[1]; saW[2] = agg[2];
    }
    __syncwarp();

    // ---- phase 5: MLP head 48->48->48->1; lane lg owns cols {lg, lg+32 (lg<16)} ----
    const int c1 = lg;
    const int c2 = (lg < 16) ? (lg + 32) : lg;  // duplicate col for lg>=16 (result unused)
    const float* saS = sm + OFF_SA + g * 48;
    const float* W1s = sm + OFF_MW1;
    float h1a = sm[OFF_MB1 + c1], h1b = sm[OFF_MB1 + c2];
    #pragma unroll 4
    for (int kk = 0; kk < 48; kk++) {
        const float sv = saS[kk];
        h1a = fmaf(sv, W1s[kk * 48 + c1], h1a);
        h1b = fmaf(sv, W1s[kk * 48 + c2], h1b);
    }
    h1a = fmaxf(h1a, 0.f); h1b = fmaxf(h1b, 0.f);
    {
        float* h1W = sm + OFF_H1 + g * 48;
        h1W[c1] = h1a;
        if (lg < 16) h1W[c2] = h1b;
    }
    __syncwarp();

    const float* h1S = sm + OFF_H1 + g * 48;
    const float* W2s = sm + OFF_MW2;
    float h2a = sm[OFF_MB2 + c1], h2b = sm[OFF_MB2 + c2];
    #pragma unroll 4
    for (int kk = 0; kk < 48; kk++) {
        const float hv = h1S[kk];
        h2a = fmaf(hv, W2s[kk * 48 + c1], h2a);
        h2b = fmaf(hv, W2s[kk * 48 + c2], h2b);
    }
    h2a = fmaxf(h2a, 0.f); h2b = fmaxf(h2b, 0.f);

    float pw = h2a * sm[OFF_MW3 + c1];
    if (lg < 16) pw = fmaf(h2b, sm[OFF_MW3 + c2], pw);
    pw += __shfl_xor_sync(0xffffffffu, pw, 16);
    pw += __shfl_xor_sync(0xffffffffu, pw, 8);
    pw += __shfl_xor_sync(0xffffffffu, pw, 4);
    pw += __shfl_xor_sync(0xffffffffu, pw, 2);
    pw += __shfl_xor_sync(0xffffffffu, pw, 1);
    if (lg == 0) out[bg] = pw + sm[OFF_MB3];
}

extern "C" void kernel_launch(void* const* d_in, const int* in_sizes, int n_in,
                              void* d_out, int out_size) {
    // metadata order: original_points(unused), data, w_qkv, pos_w1, pos_b1, pos_w2,
    // pos_b2, attn_w1, attn_b1, attn_w2, attn_b2, mlp_w1, mlp_b1, mlp_w2, mlp_b2,
    // mlp_w3, mlp_b3
    const float* data = (const float*)d_in[1];
    const float* wqkv = (const float*)d_in[2];
    const float* pw1  = (const float*)d_in[3];
    const float* pb1  = (const float*)d_in[4];
    const float* pw2  = (const float*)d_in[5];
    const float* pb2  = (const float*)d_in[6];
    const float* aw1  = (const float*)d_in[7];
    const float* ab1  = (const float*)d_in[8];
    const float* aw2  = (const float*)d_in[9];
    const float* ab2  = (const float*)d_in[10];
    const float* mw1  = (const float*)d_in[11];
    const float* mb1  = (const float*)d_in[12];
    const float* mw2  = (const float*)d_in[13];
    const float* mb2  = (const float*)d_in[14];
    const float* mw3  = (const float*)d_in[15];
    const float* mb3  = (const float*)d_in[16];
    float* out = (float*)d_out;

    const size_t smem = SMEM_FLOATS * sizeof(float);  // ~41.8 KB
    pt_kernel<<<NBLOCKS, NTHR, smem>>>(data, wqkv, pw1, pb1, pw2, pb2,
                                       aw1, ab1, aw2, ab2,
                                       mw1, mb1, mw2, mb2, mw3, mb3, out);
}

// round 3
// speedup vs baseline: 1.8218x; 1.3322x over previous
#include <cuda_runtime.h>

// Point-transformer fused kernel for GB300 (sm_103a).
// B*G = 16384 groups, 16 neighbors, dim 3.
// 32 threads per group (thread = (point i, j-half)); 4 groups per 128-thread block.
// mlp_w1 / mlp_w2 (18.4 KB) are read straight from global (L1-resident),
// NOT staged to shared: frees smem for occupancy and kills per-block staging.

#define GPB 4
#define NTHR 128
#define NBLOCKS (16384 / GPB)
#define ASTRIDE 68  // 64 + 4 pad: odd float4 stride -> conflict-free

// ---- shared memory layout (float offsets) ----
#define OFF_WQKV 0      // 27
#define OFF_PW1  32     // 192
#define OFF_PB1  224    // 64   (16B aligned)
#define OFF_PW2  288    // 192  (16B aligned)
#define OFF_PB2  480    // 3
#define OFF_AW1  484    // 36
#define OFF_AB1  520    // 12
#define OFF_AW2  532    // 36
#define OFF_AB2  568    // 3
#define OFF_MB1  572    // 48
#define OFF_MB2  620    // 48
#define OFF_MW3  668    // 48
#define OFF_MB3  716    // 1
#define OFF_A    720    // GPB * 16 * ASTRIDE = 4352
#define OFF_K    (OFF_A + GPB * 16 * ASTRIDE)   // GPB*48
#define OFF_KV   (OFF_K + GPB * 48)             // GPB*48
#define OFF_SA   (OFF_KV + GPB * 48)            // GPB*48
#define OFF_H1   (OFF_SA + GPB * 48)            // GPB*48
#define SMEM_FLOATS (OFF_H1 + GPB * 48)         // ~5840 floats = 23.4 KB

#define LOADW(PTR, OFF, N)                                        \
    for (int idx_ = tid; idx_ < (N); idx_ += NTHR) sm[(OFF) + idx_] = (PTR)[idx_];

__global__ __launch_bounds__(NTHR, 7)
void pt_kernel(const float* __restrict__ data,
               const float* __restrict__ wqkv,
               const float* __restrict__ pw1, const float* __restrict__ pb1,
               const float* __restrict__ pw2, const float* __restrict__ pb2,
               const float* __restrict__ aw1, const float* __restrict__ ab1,
               const float* __restrict__ aw2, const float* __restrict__ ab2,
               const float* __restrict__ mw1, const float* __restrict__ mb1,
               const float* __restrict__ mw2, const float* __restrict__ mb2,
               const float* __restrict__ mw3, const float* __restrict__ mb3,
               float* __restrict__ out)
{
    extern __shared__ float sm[];
    const int tid = threadIdx.x;
    const int g = tid >> 5;     // group = warp
    const int lg = tid & 31;    // lane in group
    const int i = lg & 15;      // point index
    const int half = lg >> 4;   // which 8 j's this thread owns

    // ---- phase 1a: stage only the SMALL weights into shared ----
    LOADW(wqkv, OFF_WQKV, 27)
    LOADW(pw1, OFF_PW1, 192)
    LOADW(pb1, OFF_PB1, 64)
    LOADW(pw2, OFF_PW2, 192)
    LOADW(pb2, OFF_PB2, 3)
    LOADW(aw1, OFF_AW1, 36)
    LOADW(ab1, OFF_AB1, 12)
    LOADW(aw2, OFF_AW2, 36)
    LOADW(ab2, OFF_AB2, 3)
    LOADW(mb1, OFF_MB1, 48)
    LOADW(mb2, OFF_MB2, 48)
    LOADW(mw3, OFF_MW3, 48)
    LOADW(mb3, OFF_MB3, 1)

    const int bg = blockIdx.x * GPB + g;
    const float* xp = data + (size_t)bg * 48 + i * 3;
    const float x0 = xp[0], x1 = xp[1], x2 = xp[2];

    __syncthreads();

    // ---- phase 1b: per-point q,k,v; pos-hidden a[i][h] (each half does 32 h) ----
    const float* W = sm + OFF_WQKV;  // [3][9]: q cols 0-2, k 3-5, v 6-8
    const float q0 = fmaf(x2, W[18 + 0], fmaf(x1, W[9 + 0], x0 * W[0]));
    const float q1 = fmaf(x2, W[18 + 1], fmaf(x1, W[9 + 1], x0 * W[1]));
    const float q2 = fmaf(x2, W[18 + 2], fmaf(x1, W[9 + 2], x0 * W[2]));
    const float k0 = fmaf(x2, W[18 + 3], fmaf(x1, W[9 + 3], x0 * W[3]));
    const float k1 = fmaf(x2, W[18 + 4], fmaf(x1, W[9 + 4], x0 * W[4]));
    const float k2 = fmaf(x2, W[18 + 5], fmaf(x1, W[9 + 5], x0 * W[5]));
    const float v0 = fmaf(x2, W[18 + 6], fmaf(x1, W[9 + 6], x0 * W[6]));
    const float v1 = fmaf(x2, W[18 + 7], fmaf(x1, W[9 + 7], x0 * W[7]));
    const float v2 = fmaf(x2, W[18 + 8], fmaf(x1, W[9 + 8], x0 * W[8]));

    if (half == 0) {
        float* kW = sm + OFF_K + g * 48 + i * 3;
        kW[0] = k0; kW[1] = k1; kW[2] = k2;
        float* kvW = sm + OFF_KV + g * 48 + i * 3;
        kvW[0] = k0 + v0; kvW[1] = k1 + v1; kvW[2] = k2 + v2;
    }
    {
        float* aW = sm + OFF_A + (g * 16 + i) * ASTRIDE + half * 32;
        const float* P1 = sm + OFF_PW1 + half * 32;  // [3][64] slice
        #pragma unroll 8
        for (int h = 0; h < 32; h++) {
            aW[h] = fmaf(x2, P1[128 + h], fmaf(x1, P1[64 + h], x0 * P1[h]));
        }
    }
    __syncthreads();

    // ---- phase 2: rel_emb for this thread's 8 j's (re[jj][3] in registers) ----
    float re[24];
    {
        const float pb20 = sm[OFF_PB2 + 0], pb21 = sm[OFF_PB2 + 1], pb22 = sm[OFF_PB2 + 2];
        #pragma unroll
        for (int jj = 0; jj < 8; jj++) {
            re[jj * 3 + 0] = pb20; re[jj * 3 + 1] = pb21; re[jj * 3 + 2] = pb22;
        }
    }
    {
        const float4* aJ = (const float4*)(sm + OFF_A + (g * 16 + half * 8) * ASTRIDE);
        const float4* aI = (const float4*)(sm + OFF_A + (g * 16 + i) * ASTRIDE);
        const float4* b1v4 = (const float4*)(sm + OFF_PB1);
        const float4* w2v4 = (const float4*)(sm + OFF_PW2);
        #pragma unroll 1
        for (int hq = 0; hq < 16; hq++) {
            const float4 ai = aI[hq];
            const float4 bb = b1v4[hq];
            const float ai0 = ai.x + bb.x, ai1 = ai.y + bb.y;
            const float ai2 = ai.z + bb.z, ai3 = ai.w + bb.w;
            const float4 wA = w2v4[hq * 3 + 0];
            const float4 wB = w2v4[hq * 3 + 1];
            const float4 wC = w2v4[hq * 3 + 2];
            #pragma unroll
            for (int jj = 0; jj < 8; jj++) {
                const float4 aj = aJ[jj * (ASTRIDE / 4) + hq];
                const float e0 = fmaxf(ai0 - aj.x, 0.f);
                const float e1 = fmaxf(ai1 - aj.y, 0.f);
                const float e2 = fmaxf(ai2 - aj.z, 0.f);
                const float e3 = fmaxf(ai3 - aj.w, 0.f);
                float r0 = re[jj * 3 + 0], r1 = re[jj * 3 + 1], r2 = re[jj * 3 + 2];
                r0 = fmaf(e0, wA.x, r0); r1 = fmaf(e0, wA.y, r1); r2 = fmaf(e0, wA.z, r2);
                r0 = fmaf(e1, wA.w, r0); r1 = fmaf(e1, wB.x, r1); r2 = fmaf(e1, wB.y, r2);
                r0 = fmaf(e2, wB.z, r0); r1 = fmaf(e2, wB.w, r1); r2 = fmaf(e2, wC.x, r2);
                r0 = fmaf(e3, wC.y, r0); r1 = fmaf(e3, wC.z, r1); r2 = fmaf(e3, wC.w, r2);
                re[jj * 3 + 0] = r0; re[jj * 3 + 1] = r1; re[jj * 3 + 2] = r2;
            }
        }
    }

    // ---- phase 3: t = q_i - k_j + rel_emb; attention MLP 3->12->3 ----
    const float* kS  = sm + OFF_K  + g * 48 + half * 24;
    const float* kvS = sm + OFF_KV + g * 48 + half * 24;
    #pragma unroll
    for (int jj = 0; jj < 8; jj++) {
        re[jj * 3 + 0] += q0 - kS[jj * 3 + 0];
        re[jj * 3 + 1] += q1 - kS[jj * 3 + 1];
        re[jj * 3 + 2] += q2 - kS[jj * 3 + 2];
    }
    float sim[24];
    {
        const float ab20 = sm[OFF_AB2 + 0], ab21 = sm[OFF_AB2 + 1], ab22 = sm[OFF_AB2 + 2];
        #pragma unroll
        for (int jj = 0; jj < 8; jj++) {
            sim[jj * 3 + 0] = ab20; sim[jj * 3 + 1] = ab21; sim[jj * 3 + 2] = ab22;
        }
    }
    #pragma unroll 1
    for (int c = 0; c < 12; c++) {
        const float w10 = sm[OFF_AW1 + c];
        const float w11 = sm[OFF_AW1 + 12 + c];
        const float w12 = sm[OFF_AW1 + 24 + c];
        const float bb = sm[OFF_AB1 + c];
        const float w20 = sm[OFF_AW2 + c * 3 + 0];
        const float w21 = sm[OFF_AW2 + c * 3 + 1];
        const float w22 = sm[OFF_AW2 + c * 3 + 2];
        #pragma unroll
        for (int jj = 0; jj < 8; jj++) {
            float u = fmaf(re[jj * 3 + 2], w12,
                     fmaf(re[jj * 3 + 1], w11,
                     fmaf(re[jj * 3 + 0], w10, bb)));
            u = fmaxf(u, 0.f);
            sim[jj * 3 + 0] = fmaf(u, w20, sim[jj * 3 + 0]);
            sim[jj * 3 + 1] = fmaf(u, w21, sim[jj * 3 + 1]);
            sim[jj * 3 + 2] = fmaf(u, w22, sim[jj * 3 + 2]);
        }
    }

    // ---- phase 4: softmax over 16 j (8 local + partner half via shfl) ----
    float agg[3];
    #pragma unroll
    for (int d = 0; d < 3; d++) {
        const float qd = (d == 0) ? q0 : ((d == 1) ? q1 : q2);
        float pm = sim[d];
        #pragma unroll
        for (int jj = 1; jj < 8; jj++) pm = fmaxf(pm, sim[jj * 3 + d]);
        const float m = fmaxf(pm, __shfl_xor_sync(0xffffffffu, pm, 16));
        float s = 0.f, acc = 0.f;
        #pragma unroll
        for (int jj = 0; jj < 8; jj++) {
            const float p = __expf(sim[jj * 3 + d] - m);
            s += p;
            // v_ij = v_j + rel_emb = t + (k_j + v_j) - q_i
            const float vij = re[jj * 3 + d] + kvS[jj * 3 + d] - qd;
            acc = fmaf(p, vij, acc);
        }
        s   += __shfl_xor_sync(0xffffffffu, s, 16);
        acc += __shfl_xor_sync(0xffffffffu, acc, 16);
        agg[d] = acc / s;
    }
    if (half == 0) {
        float* saW = sm + OFF_SA + g * 48 + i * 3;
        saW[0] = agg[0]; saW[1] = agg[1]; saW[2] = agg[2];
    }
    __syncwarp();

    // ---- phase 5: MLP head 48->48->48->1; lane lg owns cols {lg, lg+32 (lg<16)} ----
    // W1/W2 read directly from global: coalesced per-kk rows, L1-resident.
    const int c1 = lg;
    const int c2 = (lg < 16) ? (lg + 32) : lg;
    const float* saS = sm + OFF_SA + g * 48;
    float h1a = sm[OFF_MB1 + c1], h1b = sm[OFF_MB1 + c2];
    #pragma unroll 4
    for (int kk = 0; kk < 48; kk++) {
        const float sv = saS[kk];
        h1a = fmaf(sv, __ldg(mw1 + kk * 48 + c1), h1a);
        h1b = fmaf(sv, __ldg(mw1 + kk * 48 + c2), h1b);
    }
    h1a = fmaxf(h1a, 0.f); h1b = fmaxf(h1b, 0.f);
    {
        float* h1W = sm + OFF_H1 + g * 48;
        h1W[c1] = h1a;
        if (lg < 16) h1W[c2] = h1b;
    }
    __syncwarp();

    const float* h1S = sm + OFF_H1 + g * 48;
    float h2a = sm[OFF_MB2 + c1], h2b = sm[OFF_MB2 + c2];
    #pragma unroll 4
    for (int kk = 0; kk < 48; kk++) {
        const float hv = h1S[kk];
        h2a = fmaf(hv, __ldg(mw2 + kk * 48 + c1), h2a);
        h2b = fmaf(hv, __ldg(mw2 + kk * 48 + c2), h2b);
    }
    h2a = fmaxf(h2a, 0.f); h2b = fmaxf(h2b, 0.f);

    float pw = h2a * sm[OFF_MW3 + c1];
    if (lg < 16) pw = fmaf(h2b, sm[OFF_MW3 + c2], pw);
    pw += __shfl_xor_sync(0xffffffffu, pw, 16);
    pw += __shfl_xor_sync(0xffffffffu, pw, 8);
    pw += __shfl_xor_sync(0xffffffffu, pw, 4);
    pw += __shfl_xor_sync(0xffffffffu, pw, 2);
    pw += __shfl_xor_sync(0xffffffffu, pw, 1);
    if (lg == 0) out[bg] = pw + sm[OFF_MB3];
}

extern "C" void kernel_launch(void* const* d_in, const int* in_sizes, int n_in,
                              void* d_out, int out_size) {
    // metadata order: original_points(unused), data, w_qkv, pos_w1, pos_b1, pos_w2,
    // pos_b2, attn_w1, attn_b1, attn_w2, attn_b2, mlp_w1, mlp_b1, mlp_w2, mlp_b2,
    // mlp_w3, mlp_b3
    const float* data = (const float*)d_in[1];
    const float* wqkv = (const float*)d_in[2];
    const float* pw1  = (const float*)d_in[3];
    const float* pb1  = (const float*)d_in[4];
    const float* pw2  = (const float*)d_in[5];
    const float* pb2  = (const float*)d_in[6];
    const float* aw1  = (const float*)d_in[7];
    const float* ab1  = (const float*)d_in[8];
    const float* aw2  = (const float*)d_in[9];
    const float* ab2  = (const float*)d_in[10];
    const float* mw1  = (const float*)d_in[11];
    const float* mb1  = (const float*)d_in[12];
    const float* mw2  = (const float*)d_in[13];
    const float* mb2  = (const float*)d_in[14];
    const float* mw3  = (const float*)d_in[15];
    const float* mb3  = (const float*)d_in[16];
    float* out = (float*)d_out;

    const size_t smem = SMEM_FLOATS * sizeof(float);  // ~23.4 KB
    pt_kernel<<<NBLOCKS, NTHR, smem>>>(data, wqkv, pw1, pb1, pw2, pb2,
                                       aw1, ab1, aw2, ab2,
                                       mw1, mb1, mw2, mb2, mw3, mb3, out);
}